// round 11
// baseline (speedup 1.0000x reference)
#include <cuda_runtime.h>
#include <cuda_bf16.h>
#include <cuda_fp16.h>
#include <math_constants.h>

#define FIN 128
#define HID 64
#define NNODES 100000
#define NEDGES 1600000
#define SCAN_CHUNK 1024
#define FULLMASK 0xFFFFFFFFu

// ---------------- scratch (static device globals; no allocation) -------------
__device__ __align__(256) __half g_h[NNODES * HID];   // fp16 gather source
__device__ __align__(256) float g_agg[NNODES * HID];
__device__ __align__(256) float g_as[NNODES];
__device__ __align__(256) float g_ad[NNODES];
__device__ __align__(256) float g_eas1[NEDGES];       // as1[src] in CSR order
__device__ __align__(256) float g_eas2[NEDGES];       // as2[src] in CSR order
__device__ __align__(256) int g_deg1[NNODES],        g_deg2[NNODES];
__device__ __align__(256) int g_rp1[NNODES + 1],     g_rp2[NNODES + 1];
__device__ __align__(256) int g_cur1[NNODES],        g_cur2[NNODES];
__device__ __align__(256) int g_csr1[NEDGES],        g_csr2[NEDGES];
__device__ __align__(256) int g_bsum1[256],          g_bsum2[256];

// ---------------- GEMM + fused attention scores (device body) ----------------
// C[n,64] (fp16) = X[n,K] @ W[K,64]; tile 128x64, micro 8x4 per thread.
template <int K>
__device__ __forceinline__ void gemm_score_body(int bid,
        const float* __restrict__ X, const float* __restrict__ W,
        const float* __restrict__ att_s, const float* __restrict__ att_d,
        __half* __restrict__ C, float* __restrict__ as_, float* __restrict__ ad_,
        int n) {
    __shared__ float Xs[128][36];
    __shared__ float Ws[32][64];
    int tid = threadIdx.x;
    int tx = tid & 15;
    int ty = tid >> 4;
    int row0 = bid * 128;
    float acc[8][4] = {};
    for (int k0 = 0; k0 < K; k0 += 32) {
        for (int l = tid; l < 1024; l += 256) {
            int r = l >> 3, c4 = l & 7;
            int nd = row0 + r;
            float4 v = make_float4(0.f, 0.f, 0.f, 0.f);
            if (nd < n) v = *reinterpret_cast<const float4*>(X + (size_t)nd * K + k0 + c4 * 4);
            *reinterpret_cast<float4*>(&Xs[r][c4 * 4]) = v;
        }
        for (int l = tid; l < 512; l += 256) {
            int kk = l >> 4, c4 = l & 15;
            *reinterpret_cast<float4*>(&Ws[kk][c4 * 4]) =
                *reinterpret_cast<const float4*>(W + (size_t)(k0 + kk) * 64 + c4 * 4);
        }
        __syncthreads();
#pragma unroll
        for (int kk = 0; kk < 32; kk += 4) {
            float4 wv0 = *reinterpret_cast<float4*>(&Ws[kk + 0][tx * 4]);
            float4 wv1 = *reinterpret_cast<float4*>(&Ws[kk + 1][tx * 4]);
            float4 wv2 = *reinterpret_cast<float4*>(&Ws[kk + 2][tx * 4]);
            float4 wv3 = *reinterpret_cast<float4*>(&Ws[kk + 3][tx * 4]);
#pragma unroll
            for (int r = 0; r < 8; r++) {
                float4 xq = *reinterpret_cast<float4*>(&Xs[ty * 8 + r][kk]);
                acc[r][0] += xq.x * wv0.x; acc[r][1] += xq.x * wv0.y;
                acc[r][2] += xq.x * wv0.z; acc[r][3] += xq.x * wv0.w;
                acc[r][0] += xq.y * wv1.x; acc[r][1] += xq.y * wv1.y;
                acc[r][2] += xq.y * wv1.z; acc[r][3] += xq.y * wv1.w;
                acc[r][0] += xq.z * wv2.x; acc[r][1] += xq.z * wv2.y;
                acc[r][2] += xq.z * wv2.z; acc[r][3] += xq.z * wv2.w;
                acc[r][0] += xq.w * wv3.x; acc[r][1] += xq.w * wv3.y;
                acc[r][2] += xq.w * wv3.z; acc[r][3] += xq.w * wv3.w;
            }
        }
        __syncthreads();
    }
    float asv[4], adv[4];
#pragma unroll
    for (int c = 0; c < 4; c++) { asv[c] = att_s[tx * 4 + c]; adv[c] = att_d[tx * 4 + c]; }
#pragma unroll
    for (int r = 0; r < 8; r++) {
        int nd = row0 + ty * 8 + r;
        if (nd < n) {
            __half2 p0 = __floats2half2_rn(acc[r][0], acc[r][1]);
            __half2 p1 = __floats2half2_rn(acc[r][2], acc[r][3]);
            uint2 pk;
            pk.x = *reinterpret_cast<unsigned*>(&p0);
            pk.y = *reinterpret_cast<unsigned*>(&p1);
            *reinterpret_cast<uint2*>(C + (size_t)nd * 64 + tx * 4) = pk;
        }
        float ps = acc[r][0] * asv[0] + acc[r][1] * asv[1] + acc[r][2] * asv[2] + acc[r][3] * asv[3];
        float pd = acc[r][0] * adv[0] + acc[r][1] * adv[1] + acc[r][2] * adv[2] + acc[r][3] * adv[3];
#pragma unroll
        for (int o = 1; o < 16; o <<= 1) {
            ps += __shfl_xor_sync(FULLMASK, ps, o);
            pd += __shfl_xor_sync(FULLMASK, pd, o);
        }
        if (tx == 0 && nd < n) { as_[nd] = ps; ad_[nd] = pd; }
    }
}

// ---------------- K1: zero both degree arrays --------------------------------
__global__ void zero2_kernel(int* __restrict__ d1, int* __restrict__ d2, int n) {
    int i = blockIdx.x * blockDim.x + threadIdx.x;
    if (i < n) { d1[i] = 0; d2[i] = 0; }
}

// ---------------- K2: gemm_score layer1  ||  hist1  ||  hist2 ----------------
__global__ void gemm1_hist_kernel(const float* __restrict__ X, const float* __restrict__ W,
        const float* __restrict__ att_s, const float* __restrict__ att_d,
        __half* __restrict__ C, float* __restrict__ as_, float* __restrict__ ad_, int n,
        int gemm_blocks,
        const int* __restrict__ dst1, int* __restrict__ deg1,
        const int* __restrict__ dst2, int* __restrict__ deg2, int ne, int hb) {
    int bid = blockIdx.x;
    if (bid < gemm_blocks) {
        gemm_score_body<FIN>(bid, X, W, att_s, att_d, C, as_, ad_, n);
        return;
    }
    bid -= gemm_blocks;
    const int* dstp; int* deg;
    if (bid < hb) { dstp = dst1; deg = deg1; }
    else          { bid -= hb; dstp = dst2; deg = deg2; }
    int base = (bid * blockDim.x + threadIdx.x) * 4;
    if (base + 3 < ne) {
        int4 d4 = *reinterpret_cast<const int4*>(dstp + base);
        atomicAdd(&deg[d4.x], 1);
        atomicAdd(&deg[d4.y], 1);
        atomicAdd(&deg[d4.z], 1);
        atomicAdd(&deg[d4.w], 1);
    } else {
        for (int i = base; i < ne; i++) atomicAdd(&deg[dstp[i]], 1);
    }
}

// ---------------- K3: per-chunk scan of both degree arrays -------------------
__global__ void scan_block2_kernel(const int* __restrict__ deg1, const int* __restrict__ deg2,
                                   int* __restrict__ rp1, int* __restrict__ rp2,
                                   int* __restrict__ bs1, int* __restrict__ bs2,
                                   int n, int sb) {
    __shared__ int tsum[256];
    int b = blockIdx.x;
    const int* deg; int* rowptr; int* bsum;
    if (b < sb) { deg = deg1; rowptr = rp1; bsum = bs1; }
    else        { b -= sb; deg = deg2; rowptr = rp2; bsum = bs2; }
    int t = threadIdx.x;
    int base = b * SCAN_CHUNK + t * 4;
    int v[4]; int s = 0;
#pragma unroll
    for (int j = 0; j < 4; j++) { v[j] = (base + j < n) ? deg[base + j] : 0; s += v[j]; }
    tsum[t] = s;
    __syncthreads();
    int acc = s;
    for (int off = 1; off < 256; off <<= 1) {
        int x = (t >= off) ? tsum[t - off] : 0;
        __syncthreads();
        tsum[t] += x;
        __syncthreads();
    }
    int excl = tsum[t] - acc;
    if (t == 255) bsum[b] = tsum[255];
    int run = excl;
#pragma unroll
    for (int j = 0; j < 4; j++) {
        if (base + j < n) rowptr[base + j] = run;
        run += v[j];
    }
}

// ---------------- K4: add chunk prefixes, init cur ---------------------------
__global__ void scan_add2_kernel(int* __restrict__ rp1, int* __restrict__ cur1,
                                 const int* __restrict__ bs1,
                                 int* __restrict__ rp2, int* __restrict__ cur2,
                                 const int* __restrict__ bs2,
                                 int n, int e, int node_blocks) {
    __shared__ int red[256];
    int b = blockIdx.x;
    int* rowptr; int* cur; const int* bsum;
    if (b < node_blocks) { rowptr = rp1; cur = cur1; bsum = bs1; }
    else                 { b -= node_blocks; rowptr = rp2; cur = cur2; bsum = bs2; }
    int t = threadIdx.x;
    int c = b >> 2;
    red[t] = (t < c) ? bsum[t] : 0;
    __syncthreads();
    for (int off = 128; off; off >>= 1) {
        if (t < off) red[t] += red[t + off];
        __syncthreads();
    }
    int prefix = red[0];
    int i = b * 256 + t;
    if (i < n) {
        int v = rowptr[i] + prefix;
        rowptr[i] = v;
        cur[i] = v;
    }
    if (b == 0 && t == 0) rowptr[n] = e;
}

// ---------------- K5: scatter layer 1 + eas1 (as1[src] in CSR order) ---------
__global__ void scatter1_kernel(const int* __restrict__ src, const int* __restrict__ dst,
                                const float* __restrict__ as_,
                                int* __restrict__ cur, int* __restrict__ csr,
                                float* __restrict__ eas, int ne) {
    int base = (blockIdx.x * blockDim.x + threadIdx.x) * 4;
    if (base + 3 < ne) {
        int4 s4 = *reinterpret_cast<const int4*>(src + base);
        int4 d4 = *reinterpret_cast<const int4*>(dst + base);
        float a0 = as_[s4.x], a1 = as_[s4.y], a2 = as_[s4.z], a3 = as_[s4.w];
        int p;
        p = atomicAdd(&cur[d4.x], 1); csr[p] = s4.x; eas[p] = a0;
        p = atomicAdd(&cur[d4.y], 1); csr[p] = s4.y; eas[p] = a1;
        p = atomicAdd(&cur[d4.z], 1); csr[p] = s4.z; eas[p] = a2;
        p = atomicAdd(&cur[d4.w], 1); csr[p] = s4.w; eas[p] = a3;
    } else {
        for (int i = base; i < ne; i++) {
            int s = src[i];
            int p = atomicAdd(&cur[dst[i]], 1);
            csr[p] = s;
            eas[p] = as_[s];
        }
    }
}

// ---------------- fused single-pass softmax + aggregation (flash-style) ------
// warp per dst node; online max with rescaling; eas read coalesced, h fp16.
__device__ __forceinline__ void aggr_core(const int* __restrict__ rowptr,
                                          const int* __restrict__ csr,
                                          const float* __restrict__ eas,
                                          const float* __restrict__ ad_,
                                          const __half2* __restrict__ h2v,
                                          int nd, int lane,
                                          float& ro0, float& ro1) {
    int start = rowptr[nd];
    int end = rowptr[nd + 1];
    float adv = ad_[nd];
    float m = -CUDART_INF_F;
    float ssum = 0.f;
    float a0 = 0.f, a1 = 0.f;
    for (int base = start; base < end; base += 32) {
        int i = base + lane;
        bool valid = (i < end);
        int s = valid ? csr[i] : 0;
        float e = -CUDART_INF_F;
        if (valid) {
            float v = eas[i] + adv;               // coalesced, no chained gather
            e = (v > 0.f) ? v : 0.2f * v;
        }
        float cm = e;
#pragma unroll
        for (int o = 16; o; o >>= 1) cm = fmaxf(cm, __shfl_xor_sync(FULLMASK, cm, o));
        float mnew = fmaxf(m, cm);
        float scale = __expf(m - mnew);
        ssum *= scale; a0 *= scale; a1 *= scale;
        float w = valid ? __expf(e - mnew) : 0.f;
        float ws = w;
#pragma unroll
        for (int o = 16; o; o >>= 1) ws += __shfl_xor_sync(FULLMASK, ws, o);
        ssum += ws;
        m = mnew;
        int cnt = min(32, end - base);
        for (int j = 0; j < cnt; j += 8) {          // invalid lanes carry w=0, s=0
            float wv[8]; __half2 hr[8];
#pragma unroll
            for (int k = 0; k < 8; k++) {
                int sj = __shfl_sync(FULLMASK, s, j + k);
                wv[k] = __shfl_sync(FULLMASK, w, j + k);
                hr[k] = h2v[(size_t)sj * 32 + lane];
            }
#pragma unroll
            for (int k = 0; k < 8; k++) {
                float2 hv = __half22float2(hr[k]);
                a0 += wv[k] * hv.x;
                a1 += wv[k] * hv.y;
            }
        }
    }
    float inv = 1.f / (ssum + 1e-16f);
    ro0 = a0 * inv;
    ro1 = a1 * inv;
}

// ---------------- K6: aggr layer1 (+bias+relu)  ||  scatter layer2 -----------
__global__ void aggr_scatter_kernel(const int* __restrict__ rowptr, const int* __restrict__ csr,
        const float* __restrict__ eas, const float* __restrict__ ad_,
        const __half2* __restrict__ h2v, const float* __restrict__ bias,
        float* __restrict__ aggout, int n, int warp_blocks,
        const int* __restrict__ src2, const int* __restrict__ dst2,
        int* __restrict__ cur2, int* __restrict__ csr2, int ne) {
    int b = blockIdx.x;
    if (b >= warp_blocks) {                 // scatter for layer 2 (src only)
        b -= warp_blocks;
        int i = b * blockDim.x + threadIdx.x;
        if (i < ne) {
            int d = dst2[i];
            int p = atomicAdd(&cur2[d], 1);
            csr2[p] = src2[i];
        }
        return;
    }
    int gt = b * blockDim.x + threadIdx.x;
    int nd = gt >> 5;
    int lane = gt & 31;
    if (nd >= n) return;
    float o0, o1;
    aggr_core(rowptr, csr, eas, ad_, h2v, nd, lane, o0, o1);
    o0 = fmaxf(o0 + bias[lane * 2], 0.f);
    o1 = fmaxf(o1 + bias[lane * 2 + 1], 0.f);
    *reinterpret_cast<float2*>(aggout + (size_t)nd * 64 + lane * 2) = make_float2(o0, o1);
}

// ---------------- K7: gemm_score layer2 --------------------------------------
__global__ void gemm2_kernel(const float* __restrict__ X, const float* __restrict__ W,
        const float* __restrict__ att_s, const float* __restrict__ att_d,
        __half* __restrict__ C, float* __restrict__ as_, float* __restrict__ ad_, int n) {
    gemm_score_body<HID>(blockIdx.x, X, W, att_s, att_d, C, as_, ad_, n);
}

// ---------------- K7.5: eas2[i] = as2[csr2[i]] (CSR-order gather) ------------
__global__ void eas2_kernel(const int* __restrict__ csr, const float* __restrict__ as_,
                            float* __restrict__ eas, int ne) {
    int base = (blockIdx.x * blockDim.x + threadIdx.x) * 4;
    if (base + 3 < ne) {
        int4 s4 = *reinterpret_cast<const int4*>(csr + base);
        float4 v = make_float4(as_[s4.x], as_[s4.y], as_[s4.z], as_[s4.w]);
        *reinterpret_cast<float4*>(eas + base) = v;
    } else {
        for (int i = base; i < ne; i++) eas[i] = as_[csr[i]];
    }
}

// ---------------- K8: aggr layer2 + bias + linear + log_softmax --------------
__global__ void aggr_final_kernel(const int* __restrict__ rowptr, const int* __restrict__ csr,
        const float* __restrict__ eas, const float* __restrict__ ad_,
        const __half2* __restrict__ h2v, const float* __restrict__ bias,
        const float* __restrict__ Wlin, const float* __restrict__ blin,
        float* __restrict__ out, int n) {
    __shared__ float Ws[64 * 32];
    for (int i = threadIdx.x; i < 64 * 32; i += blockDim.x) Ws[i] = Wlin[i];
    __syncthreads();
    int gt = blockIdx.x * blockDim.x + threadIdx.x;
    int nd = gt >> 5;
    int lane = gt & 31;
    if (nd >= n) return;
    float o0, o1;
    aggr_core(rowptr, csr, eas, ad_, h2v, nd, lane, o0, o1);
    o0 += bias[lane * 2];
    o1 += bias[lane * 2 + 1];
    float y = blin[lane];
#pragma unroll
    for (int j = 0; j < 32; j++) {
        float r0 = __shfl_sync(FULLMASK, o0, j);
        float r1 = __shfl_sync(FULLMASK, o1, j);
        y += r0 * Ws[(2 * j) * 32 + lane] + r1 * Ws[(2 * j + 1) * 32 + lane];
    }
    float m = y;
#pragma unroll
    for (int o = 16; o; o >>= 1) m = fmaxf(m, __shfl_xor_sync(FULLMASK, m, o));
    float ex = __expf(y - m);
    float ss = ex;
#pragma unroll
    for (int o = 16; o; o >>= 1) ss += __shfl_xor_sync(FULLMASK, ss, o);
    out[(size_t)nd * 32 + lane] = y - m - __logf(ss);
}

// ---------------- launch ------------------------------------------------------
extern "C" void kernel_launch(void* const* d_in, const int* in_sizes, int n_in,
                              void* d_out, int out_size) {
    const float* x        = (const float*)d_in[0];
    const int*   ei1      = (const int*)d_in[1];
    const int*   ei2      = (const int*)d_in[2];
    const float* W1       = (const float*)d_in[3];
    const float* att_src1 = (const float*)d_in[4];
    const float* att_dst1 = (const float*)d_in[5];
    const float* b1       = (const float*)d_in[6];
    const float* W2       = (const float*)d_in[7];
    const float* att_src2 = (const float*)d_in[8];
    const float* att_dst2 = (const float*)d_in[9];
    const float* b2       = (const float*)d_in[10];
    const float* Wlin     = (const float*)d_in[11];
    const float* blin     = (const float*)d_in[12];
    float* out = (float*)d_out;

    const int n = in_sizes[0] / FIN;       // 100000
    const int e = in_sizes[1] / 2;         // 1600000

    __half* h;
    float *agg, *as_, *ad_, *eas1, *eas2;
    int *deg1, *rp1, *cur1, *csr1, *bs1;
    int *deg2, *rp2, *cur2, *csr2, *bs2;
    cudaGetSymbolAddress((void**)&h,    g_h);
    cudaGetSymbolAddress((void**)&agg,  g_agg);
    cudaGetSymbolAddress((void**)&as_,  g_as);
    cudaGetSymbolAddress((void**)&ad_,  g_ad);
    cudaGetSymbolAddress((void**)&eas1, g_eas1);
    cudaGetSymbolAddress((void**)&eas2, g_eas2);
    cudaGetSymbolAddress((void**)&deg1, g_deg1);
    cudaGetSymbolAddress((void**)&rp1,  g_rp1);
    cudaGetSymbolAddress((void**)&cur1, g_cur1);
    cudaGetSymbolAddress((void**)&csr1, g_csr1);
    cudaGetSymbolAddress((void**)&bs1,  g_bsum1);
    cudaGetSymbolAddress((void**)&deg2, g_deg2);
    cudaGetSymbolAddress((void**)&rp2,  g_rp2);
    cudaGetSymbolAddress((void**)&cur2, g_cur2);
    cudaGetSymbolAddress((void**)&csr2, g_csr2);
    cudaGetSymbolAddress((void**)&bs2,  g_bsum2);
    const __half2* h2v = (const __half2*)h;

    const int TB = 256;
    int gemm_blocks = (n + 127) / 128;                   // 782
    int node_blocks = (n + TB - 1) / TB;                 // 391
    int warp_blocks = (n * 32 + TB - 1) / TB;            // 12500
    int eb          = (e + TB - 1) / TB;                 // 6250
    int hb          = (e + 4 * TB - 1) / (4 * TB);       // 1563
    int sb          = (n + SCAN_CHUNK - 1) / SCAN_CHUNK; // 98

    // K1: zero degree arrays
    zero2_kernel<<<node_blocks, TB>>>(deg1, deg2, n);
    // K2: gemm1+score1 || hist1 || hist2
    gemm1_hist_kernel<<<gemm_blocks + 2 * hb, TB>>>(
        x, W1, att_src1, att_dst1, h, as_, ad_, n, gemm_blocks,
        ei1 + e, deg1, ei2 + e, deg2, e, hb);
    // K3/K4: rowptr scans (both layers)
    scan_block2_kernel<<<2 * sb, TB>>>(deg1, deg2, rp1, rp2, bs1, bs2, n, sb);
    scan_add2_kernel<<<2 * node_blocks, TB>>>(rp1, cur1, bs1, rp2, cur2, bs2, n, e, node_blocks);
    // K5: scatter layer 1 + eas1
    scatter1_kernel<<<hb, TB>>>(ei1, ei1 + e, as_, cur1, csr1, eas1, e);
    // K6: aggr layer1 (+bias+relu)  ||  scatter layer 2
    aggr_scatter_kernel<<<warp_blocks + eb, TB>>>(
        rp1, csr1, eas1, ad_, h2v, b1, agg, n, warp_blocks,
        ei2, ei2 + e, cur2, csr2, e);
    // K7: gemm2+score2
    gemm2_kernel<<<gemm_blocks, TB>>>(agg, W2, att_src2, att_dst2, h, as_, ad_, n);
    // K7.5: eas2 = as2[csr2] in CSR order
    eas2_kernel<<<hb, TB>>>(csr2, as_, eas2, e);
    // K8: aggr layer2 + linear + log_softmax
    aggr_final_kernel<<<warp_blocks, TB>>>(
        rp2, csr2, eas2, ad_, h2v, b2, Wlin, blin, out, n);
}

// round 12
// speedup vs baseline: 1.1041x; 1.1041x over previous
#include <cuda_runtime.h>
#include <cuda_bf16.h>
#include <cuda_fp16.h>
#include <math_constants.h>

#define FIN 128
#define HID 64
#define NNODES 100000
#define NEDGES 1600000
#define SCAN_CHUNK 1024
#define FULLMASK 0xFFFFFFFFu

// ---------------- scratch (static device globals; no allocation) -------------
__device__ __align__(256) __half g_h[NNODES * HID];   // fp16 gather source
__device__ __align__(256) float g_agg[NNODES * HID];
__device__ __align__(256) float g_as[NNODES];
__device__ __align__(256) float g_ad[NNODES];
__device__ __align__(256) int g_deg1[NNODES],        g_deg2[NNODES];
__device__ __align__(256) int g_rp1[NNODES + 1],     g_rp2[NNODES + 1];
__device__ __align__(256) int g_cur1[NNODES],        g_cur2[NNODES];
__device__ __align__(256) int g_csr1[NEDGES],        g_csr2[NEDGES];
__device__ __align__(256) int g_bsum1[256],          g_bsum2[256];

// ---------------- tf32 helpers ------------------------------------------------
__device__ __forceinline__ unsigned f2tf32(float f) {
    unsigned u;
    asm("cvt.rna.tf32.f32 %0, %1;" : "=r"(u) : "f"(f));
    return u;
}
__device__ __forceinline__ void mma_tf32(float& c0, float& c1, float& c2, float& c3,
                                         unsigned a0, unsigned a1, unsigned a2, unsigned a3,
                                         unsigned b0, unsigned b1) {
    asm volatile(
        "mma.sync.aligned.m16n8k8.row.col.f32.tf32.tf32.f32 "
        "{%0,%1,%2,%3}, {%4,%5,%6,%7}, {%8,%9}, {%0,%1,%2,%3};"
        : "+f"(c0), "+f"(c1), "+f"(c2), "+f"(c3)
        : "r"(a0), "r"(a1), "r"(a2), "r"(a3), "r"(b0), "r"(b1));
}

// ---------------- GEMM (tf32 MMA) + fused attention scores --------------------
// C[n,64] (fp16) = X[n,K] @ W[K,64]; block tile 128x64; warp w owns rows
// [w*16, w*16+16), 8 col-tiles of 8. fp32 accumulators; scores from fp32 accs.
template <int K>
__device__ __forceinline__ void gemm_score_body(int bid,
        const float* __restrict__ X, const float* __restrict__ W,
        const float* __restrict__ att_s, const float* __restrict__ att_d,
        __half* __restrict__ C, float* __restrict__ as_, float* __restrict__ ad_,
        int n) {
    __shared__ float Xs[128][36];    // [row][kk in chunk], padded
    __shared__ float Ws[32][72];     // [kk][col], padded to 72 (8 mod 32) for
                                     // conflict-free B-fragment loads
    int tid = threadIdx.x;
    int w = tid >> 5;
    int lane = tid & 31;
    int g = lane >> 2;               // 0..7  (row within 16-row tile; +8 pair)
    int tg = lane & 3;               // 0..3  (k / col sub-index)
    int row0 = bid * 128;
    float acc[8][4] = {};            // 8 col-tiles x {r,c}{g,g+8} pairs
    for (int k0 = 0; k0 < K; k0 += 32) {
        // X chunk: 128 rows x 32 k (1024 float4)
        for (int l = tid; l < 1024; l += 256) {
            int r = l >> 3, c4 = l & 7;
            int nd = row0 + r;
            float4 v = make_float4(0.f, 0.f, 0.f, 0.f);
            if (nd < n) v = *reinterpret_cast<const float4*>(X + (size_t)nd * K + k0 + c4 * 4);
            *reinterpret_cast<float4*>(&Xs[r][c4 * 4]) = v;
        }
        // W chunk: 32 kk x 64 cols (512 float4)
        for (int l = tid; l < 512; l += 256) {
            int kk = l >> 4, c4 = l & 15;
            *reinterpret_cast<float4*>(&Ws[kk][c4 * 4]) =
                *reinterpret_cast<const float4*>(W + (size_t)(k0 + kk) * 64 + c4 * 4);
        }
        __syncthreads();
#pragma unroll
        for (int kk = 0; kk < 32; kk += 8) {
            // A fragment (16x8 row-major): rows w*16+g / +8, cols kk+tg / +4
            unsigned a0 = f2tf32(Xs[w * 16 + g][kk + tg]);
            unsigned a1 = f2tf32(Xs[w * 16 + g + 8][kk + tg]);
            unsigned a2 = f2tf32(Xs[w * 16 + g][kk + tg + 4]);
            unsigned a3 = f2tf32(Xs[w * 16 + g + 8][kk + tg + 4]);
#pragma unroll
            for (int ct = 0; ct < 8; ct++) {
                // B fragment (8x8, k x n col-major): B[k][nc] = Ws[kk+k][ct*8+nc]
                unsigned b0 = f2tf32(Ws[kk + tg][ct * 8 + g]);
                unsigned b1 = f2tf32(Ws[kk + tg + 4][ct * 8 + g]);
                mma_tf32(acc[ct][0], acc[ct][1], acc[ct][2], acc[ct][3],
                         a0, a1, a2, a3, b0, b1);
            }
        }
        __syncthreads();
    }
    // Epilogue: thread owns C[row_g][ct*8+2tg .. +1] (acc[ct][0..1]) and
    // C[row_g8][...] (acc[ct][2..3]).
    int row_g = row0 + w * 16 + g;
    int row_g8 = row_g + 8;
    float ps_g = 0.f, pd_g = 0.f, ps_g8 = 0.f, pd_g8 = 0.f;
#pragma unroll
    for (int ct = 0; ct < 8; ct++) {
        int c0i = ct * 8 + 2 * tg;
        float s0 = att_s[c0i], s1 = att_s[c0i + 1];
        float d0 = att_d[c0i], d1 = att_d[c0i + 1];
        ps_g  += acc[ct][0] * s0 + acc[ct][1] * s1;
        pd_g  += acc[ct][0] * d0 + acc[ct][1] * d1;
        ps_g8 += acc[ct][2] * s0 + acc[ct][3] * s1;
        pd_g8 += acc[ct][2] * d0 + acc[ct][3] * d1;
    }
    // reduce over the 4 lanes (tg) sharing each row
#pragma unroll
    for (int o = 1; o < 4; o <<= 1) {
        ps_g  += __shfl_xor_sync(FULLMASK, ps_g, o);
        pd_g  += __shfl_xor_sync(FULLMASK, pd_g, o);
        ps_g8 += __shfl_xor_sync(FULLMASK, ps_g8, o);
        pd_g8 += __shfl_xor_sync(FULLMASK, pd_g8, o);
    }
    if (row_g < n) {
#pragma unroll
        for (int ct = 0; ct < 8; ct++) {
            __half2 p = __floats2half2_rn(acc[ct][0], acc[ct][1]);
            *reinterpret_cast<__half2*>(C + (size_t)row_g * 64 + ct * 8 + 2 * tg) = p;
        }
        if (tg == 0) { as_[row_g] = ps_g; ad_[row_g] = pd_g; }
    }
    if (row_g8 < n) {
#pragma unroll
        for (int ct = 0; ct < 8; ct++) {
            __half2 p = __floats2half2_rn(acc[ct][2], acc[ct][3]);
            *reinterpret_cast<__half2*>(C + (size_t)row_g8 * 64 + ct * 8 + 2 * tg) = p;
        }
        if (tg == 0) { as_[row_g8] = ps_g8; ad_[row_g8] = pd_g8; }
    }
}

// ---------------- K1: zero both degree arrays --------------------------------
__global__ void zero2_kernel(int* __restrict__ d1, int* __restrict__ d2, int n) {
    int i = blockIdx.x * blockDim.x + threadIdx.x;
    if (i < n) { d1[i] = 0; d2[i] = 0; }
}

// ---------------- K2: gemm_score layer1  ||  hist1  ||  hist2 ----------------
__global__ void gemm1_hist_kernel(const float* __restrict__ X, const float* __restrict__ W,
        const float* __restrict__ att_s, const float* __restrict__ att_d,
        __half* __restrict__ C, float* __restrict__ as_, float* __restrict__ ad_, int n,
        int gemm_blocks,
        const int* __restrict__ dst1, int* __restrict__ deg1,
        const int* __restrict__ dst2, int* __restrict__ deg2, int ne, int hb) {
    int bid = blockIdx.x;
    if (bid < gemm_blocks) {
        gemm_score_body<FIN>(bid, X, W, att_s, att_d, C, as_, ad_, n);
        return;
    }
    bid -= gemm_blocks;
    const int* dstp; int* deg;
    if (bid < hb) { dstp = dst1; deg = deg1; }
    else          { bid -= hb; dstp = dst2; deg = deg2; }
    int base = (bid * blockDim.x + threadIdx.x) * 4;
    if (base + 3 < ne) {
        int4 d4 = *reinterpret_cast<const int4*>(dstp + base);
        atomicAdd(&deg[d4.x], 1);
        atomicAdd(&deg[d4.y], 1);
        atomicAdd(&deg[d4.z], 1);
        atomicAdd(&deg[d4.w], 1);
    } else {
        for (int i = base; i < ne; i++) atomicAdd(&deg[dstp[i]], 1);
    }
}

// ---------------- K3: per-chunk scan of both degree arrays -------------------
__global__ void scan_block2_kernel(const int* __restrict__ deg1, const int* __restrict__ deg2,
                                   int* __restrict__ rp1, int* __restrict__ rp2,
                                   int* __restrict__ bs1, int* __restrict__ bs2,
                                   int n, int sb) {
    __shared__ int tsum[256];
    int b = blockIdx.x;
    const int* deg; int* rowptr; int* bsum;
    if (b < sb) { deg = deg1; rowptr = rp1; bsum = bs1; }
    else        { b -= sb; deg = deg2; rowptr = rp2; bsum = bs2; }
    int t = threadIdx.x;
    int base = b * SCAN_CHUNK + t * 4;
    int v[4]; int s = 0;
#pragma unroll
    for (int j = 0; j < 4; j++) { v[j] = (base + j < n) ? deg[base + j] : 0; s += v[j]; }
    tsum[t] = s;
    __syncthreads();
    int acc = s;
    for (int off = 1; off < 256; off <<= 1) {
        int x = (t >= off) ? tsum[t - off] : 0;
        __syncthreads();
        tsum[t] += x;
        __syncthreads();
    }
    int excl = tsum[t] - acc;
    if (t == 255) bsum[b] = tsum[255];
    int run = excl;
#pragma unroll
    for (int j = 0; j < 4; j++) {
        if (base + j < n) rowptr[base + j] = run;
        run += v[j];
    }
}

// ---------------- K4: add chunk prefixes, init cur ---------------------------
__global__ void scan_add2_kernel(int* __restrict__ rp1, int* __restrict__ cur1,
                                 const int* __restrict__ bs1,
                                 int* __restrict__ rp2, int* __restrict__ cur2,
                                 const int* __restrict__ bs2,
                                 int n, int e, int node_blocks) {
    __shared__ int red[256];
    int b = blockIdx.x;
    int* rowptr; int* cur; const int* bsum;
    if (b < node_blocks) { rowptr = rp1; cur = cur1; bsum = bs1; }
    else                 { b -= node_blocks; rowptr = rp2; cur = cur2; bsum = bs2; }
    int t = threadIdx.x;
    int c = b >> 2;
    red[t] = (t < c) ? bsum[t] : 0;
    __syncthreads();
    for (int off = 128; off; off >>= 1) {
        if (t < off) red[t] += red[t + off];
        __syncthreads();
    }
    int prefix = red[0];
    int i = b * 256 + t;
    if (i < n) {
        int v = rowptr[i] + prefix;
        rowptr[i] = v;
        cur[i] = v;
    }
    if (b == 0 && t == 0) rowptr[n] = e;
}

// ---------------- K5: scatter layer 1 (int4, 4 edges/thread) -----------------
__global__ void scatter1_kernel(const int* __restrict__ src, const int* __restrict__ dst,
                                int* __restrict__ cur, int* __restrict__ csr, int ne) {
    int base = (blockIdx.x * blockDim.x + threadIdx.x) * 4;
    if (base + 3 < ne) {
        int4 s4 = *reinterpret_cast<const int4*>(src + base);
        int4 d4 = *reinterpret_cast<const int4*>(dst + base);
        int p;
        p = atomicAdd(&cur[d4.x], 1); csr[p] = s4.x;
        p = atomicAdd(&cur[d4.y], 1); csr[p] = s4.y;
        p = atomicAdd(&cur[d4.z], 1); csr[p] = s4.z;
        p = atomicAdd(&cur[d4.w], 1); csr[p] = s4.w;
    } else {
        for (int i = base; i < ne; i++) {
            int p = atomicAdd(&cur[dst[i]], 1);
            csr[p] = src[i];
        }
    }
}

// ---------------- fused single-pass softmax + aggregation (flash-style) ------
// warp per dst node; online max with accumulator rescaling; h gathered as fp16.
__device__ __forceinline__ void aggr_core(const int* __restrict__ rowptr,
                                          const int* __restrict__ csr,
                                          const float* __restrict__ as_,
                                          const float* __restrict__ ad_,
                                          const __half2* __restrict__ h2v,
                                          int nd, int lane,
                                          float& ro0, float& ro1) {
    int start = rowptr[nd];
    int end = rowptr[nd + 1];
    float adv = ad_[nd];
    float m = -CUDART_INF_F;
    float ssum = 0.f;
    float a0 = 0.f, a1 = 0.f;
    for (int base = start; base < end; base += 32) {
        int i = base + lane;
        bool valid = (i < end);
        int s = valid ? csr[i] : 0;
        float e = -CUDART_INF_F;
        if (valid) {
            float v = as_[s] + adv;
            e = (v > 0.f) ? v : 0.2f * v;
        }
        float cm = e;
#pragma unroll
        for (int o = 16; o; o >>= 1) cm = fmaxf(cm, __shfl_xor_sync(FULLMASK, cm, o));
        float mnew = fmaxf(m, cm);
        float scale = __expf(m - mnew);
        ssum *= scale; a0 *= scale; a1 *= scale;
        float w = valid ? __expf(e - mnew) : 0.f;
        float ws = w;
#pragma unroll
        for (int o = 16; o; o >>= 1) ws += __shfl_xor_sync(FULLMASK, ws, o);
        ssum += ws;
        m = mnew;
        int cnt = min(32, end - base);
        for (int j = 0; j < cnt; j += 8) {          // invalid lanes carry w=0, s=0
            float wv[8]; __half2 hr[8];
#pragma unroll
            for (int k = 0; k < 8; k++) {
                int sj = __shfl_sync(FULLMASK, s, j + k);
                wv[k] = __shfl_sync(FULLMASK, w, j + k);
                hr[k] = h2v[(size_t)sj * 32 + lane];
            }
#pragma unroll
            for (int k = 0; k < 8; k++) {
                float2 hv = __half22float2(hr[k]);
                a0 += wv[k] * hv.x;
                a1 += wv[k] * hv.y;
            }
        }
    }
    float inv = 1.f / (ssum + 1e-16f);
    ro0 = a0 * inv;
    ro1 = a1 * inv;
}

// ---------------- K6: aggr layer1 (+bias+relu)  ||  scatter layer2 -----------
__global__ void aggr_scatter_kernel(const int* __restrict__ rowptr, const int* __restrict__ csr,
        const float* __restrict__ as_, const float* __restrict__ ad_,
        const __half2* __restrict__ h2v, const float* __restrict__ bias,
        float* __restrict__ aggout, int n, int warp_blocks,
        const int* __restrict__ src2, const int* __restrict__ dst2,
        int* __restrict__ cur2, int* __restrict__ csr2, int ne) {
    int b = blockIdx.x;
    if (b >= warp_blocks) {                 // scatter for layer 2
        b -= warp_blocks;
        int i = b * blockDim.x + threadIdx.x;
        if (i < ne) {
            int d = dst2[i];
            int p = atomicAdd(&cur2[d], 1);
            csr2[p] = src2[i];
        }
        return;
    }
    int gt = b * blockDim.x + threadIdx.x;
    int nd = gt >> 5;
    int lane = gt & 31;
    if (nd >= n) return;
    float o0, o1;
    aggr_core(rowptr, csr, as_, ad_, h2v, nd, lane, o0, o1);
    o0 = fmaxf(o0 + bias[lane * 2], 0.f);
    o1 = fmaxf(o1 + bias[lane * 2 + 1], 0.f);
    *reinterpret_cast<float2*>(aggout + (size_t)nd * 64 + lane * 2) = make_float2(o0, o1);
}

// ---------------- K7: gemm_score layer2 --------------------------------------
__global__ void gemm2_kernel(const float* __restrict__ X, const float* __restrict__ W,
        const float* __restrict__ att_s, const float* __restrict__ att_d,
        __half* __restrict__ C, float* __restrict__ as_, float* __restrict__ ad_, int n) {
    gemm_score_body<HID>(blockIdx.x, X, W, att_s, att_d, C, as_, ad_, n);
}

// ---------------- K8: aggr layer2 + bias + linear + log_softmax --------------
__global__ void aggr_final_kernel(const int* __restrict__ rowptr, const int* __restrict__ csr,
        const float* __restrict__ as_, const float* __restrict__ ad_,
        const __half2* __restrict__ h2v, const float* __restrict__ bias,
        const float* __restrict__ Wlin, const float* __restrict__ blin,
        float* __restrict__ out, int n) {
    __shared__ float Ws[64 * 32];
    for (int i = threadIdx.x; i < 64 * 32; i += blockDim.x) Ws[i] = Wlin[i];
    __syncthreads();
    int gt = blockIdx.x * blockDim.x + threadIdx.x;
    int nd = gt >> 5;
    int lane = gt & 31;
    if (nd >= n) return;
    float o0, o1;
    aggr_core(rowptr, csr, as_, ad_, h2v, nd, lane, o0, o1);
    o0 += bias[lane * 2];
    o1 += bias[lane * 2 + 1];
    float y = blin[lane];
#pragma unroll
    for (int j = 0; j < 32; j++) {
        float r0 = __shfl_sync(FULLMASK, o0, j);
        float r1 = __shfl_sync(FULLMASK, o1, j);
        y += r0 * Ws[(2 * j) * 32 + lane] + r1 * Ws[(2 * j + 1) * 32 + lane];
    }
    float m = y;
#pragma unroll
    for (int o = 16; o; o >>= 1) m = fmaxf(m, __shfl_xor_sync(FULLMASK, m, o));
    float ex = __expf(y - m);
    float ss = ex;
#pragma unroll
    for (int o = 16; o; o >>= 1) ss += __shfl_xor_sync(FULLMASK, ss, o);
    out[(size_t)nd * 32 + lane] = y - m - __logf(ss);
}

// ---------------- launch ------------------------------------------------------
extern "C" void kernel_launch(void* const* d_in, const int* in_sizes, int n_in,
                              void* d_out, int out_size) {
    const float* x        = (const float*)d_in[0];
    const int*   ei1      = (const int*)d_in[1];
    const int*   ei2      = (const int*)d_in[2];
    const float* W1       = (const float*)d_in[3];
    const float* att_src1 = (const float*)d_in[4];
    const float* att_dst1 = (const float*)d_in[5];
    const float* b1       = (const float*)d_in[6];
    const float* W2       = (const float*)d_in[7];
    const float* att_src2 = (const float*)d_in[8];
    const float* att_dst2 = (const float*)d_in[9];
    const float* b2       = (const float*)d_in[10];
    const float* Wlin     = (const float*)d_in[11];
    const float* blin     = (const float*)d_in[12];
    float* out = (float*)d_out;

    const int n = in_sizes[0] / FIN;       // 100000
    const int e = in_sizes[1] / 2;         // 1600000

    __half* h;
    float *agg, *as_, *ad_;
    int *deg1, *rp1, *cur1, *csr1, *bs1;
    int *deg2, *rp2, *cur2, *csr2, *bs2;
    cudaGetSymbolAddress((void**)&h,    g_h);
    cudaGetSymbolAddress((void**)&agg,  g_agg);
    cudaGetSymbolAddress((void**)&as_,  g_as);
    cudaGetSymbolAddress((void**)&ad_,  g_ad);
    cudaGetSymbolAddress((void**)&deg1, g_deg1);
    cudaGetSymbolAddress((void**)&rp1,  g_rp1);
    cudaGetSymbolAddress((void**)&cur1, g_cur1);
    cudaGetSymbolAddress((void**)&csr1, g_csr1);
    cudaGetSymbolAddress((void**)&bs1,  g_bsum1);
    cudaGetSymbolAddress((void**)&deg2, g_deg2);
    cudaGetSymbolAddress((void**)&rp2,  g_rp2);
    cudaGetSymbolAddress((void**)&cur2, g_cur2);
    cudaGetSymbolAddress((void**)&csr2, g_csr2);
    cudaGetSymbolAddress((void**)&bs2,  g_bsum2);
    const __half2* h2v = (const __half2*)h;

    const int TB = 256;
    int gemm_blocks = (n + 127) / 128;                   // 782
    int node_blocks = (n + TB - 1) / TB;                 // 391
    int warp_blocks = (n * 32 + TB - 1) / TB;            // 12500
    int eb          = (e + TB - 1) / TB;                 // 6250
    int hb          = (e + 4 * TB - 1) / (4 * TB);       // 1563
    int sb          = (n + SCAN_CHUNK - 1) / SCAN_CHUNK; // 98

    // K1: zero degree arrays
    zero2_kernel<<<node_blocks, TB>>>(deg1, deg2, n);
    // K2: gemm1+score1 || hist1 || hist2
    gemm1_hist_kernel<<<gemm_blocks + 2 * hb, TB>>>(
        x, W1, att_src1, att_dst1, h, as_, ad_, n, gemm_blocks,
        ei1 + e, deg1, ei2 + e, deg2, e, hb);
    // K3/K4: rowptr scans (both layers)
    scan_block2_kernel<<<2 * sb, TB>>>(deg1, deg2, rp1, rp2, bs1, bs2, n, sb);
    scan_add2_kernel<<<2 * node_blocks, TB>>>(rp1, cur1, bs1, rp2, cur2, bs2, n, e, node_blocks);
    // K5: scatter layer 1 (int4)
    scatter1_kernel<<<hb, TB>>>(ei1, ei1 + e, cur1, csr1, e);
    // K6: aggr layer1 (+bias+relu)  ||  scatter layer 2
    aggr_scatter_kernel<<<warp_blocks + eb, TB>>>(
        rp1, csr1, as_, ad_, h2v, b1, agg, n, warp_blocks,
        ei2, ei2 + e, cur2, csr2, e);
    // K7: gemm2+score2
    gemm2_kernel<<<gemm_blocks, TB>>>(agg, W2, att_src2, att_dst2, h, as_, ad_, n);
    // K8: aggr layer2 + linear + log_softmax
    aggr_final_kernel<<<warp_blocks, TB>>>(
        rp2, csr2, as_, ad_, h2v, b2, Wlin, blin, out, n);
}

// round 13
// speedup vs baseline: 1.3090x; 1.1856x over previous
#include <cuda_runtime.h>
#include <cuda_bf16.h>
#include <cuda_fp16.h>
#include <math_constants.h>

#define FIN 128
#define HID 64
#define NNODES 100000
#define NEDGES 1600000
#define SCAN_CHUNK 1024
#define FULLMASK 0xFFFFFFFFu

// ---------------- scratch (static device globals; no allocation) -------------
__device__ __align__(256) __half g_h[NNODES * HID];   // fp16 gather source
__device__ __align__(256) float g_agg[NNODES * HID];
__device__ __align__(256) float g_as[NNODES];
__device__ __align__(256) float g_ad[NNODES];
__device__ __align__(256) int g_deg1[NNODES],        g_deg2[NNODES];
__device__ __align__(256) int g_rp1[NNODES + 1],     g_rp2[NNODES + 1];
__device__ __align__(256) int g_cur1[NNODES],        g_cur2[NNODES];
__device__ __align__(256) int g_csr1[NEDGES],        g_csr2[NEDGES];
__device__ __align__(256) int g_bsum1[256],          g_bsum2[256];

// ---------------- tf32 helpers ------------------------------------------------
__device__ __forceinline__ unsigned f2tf32(float f) {
    unsigned u;
    asm("cvt.rna.tf32.f32 %0, %1;" : "=r"(u) : "f"(f));
    return u;
}
__device__ __forceinline__ void mma_tf32(float& c0, float& c1, float& c2, float& c3,
                                         unsigned a0, unsigned a1, unsigned a2, unsigned a3,
                                         unsigned b0, unsigned b1) {
    asm volatile(
        "mma.sync.aligned.m16n8k8.row.col.f32.tf32.tf32.f32 "
        "{%0,%1,%2,%3}, {%4,%5,%6,%7}, {%8,%9}, {%0,%1,%2,%3};"
        : "+f"(c0), "+f"(c1), "+f"(c2), "+f"(c3)
        : "r"(a0), "r"(a1), "r"(a2), "r"(a3), "r"(b0), "r"(b1));
}

// ---------------- GEMM (tf32 MMA) + fused attention scores --------------------
template <int K>
__device__ __forceinline__ void gemm_score_body(int bid,
        const float* __restrict__ X, const float* __restrict__ W,
        const float* __restrict__ att_s, const float* __restrict__ att_d,
        __half* __restrict__ C, float* __restrict__ as_, float* __restrict__ ad_,
        int n) {
    __shared__ float Xs[128][36];
    __shared__ float Ws[32][72];
    int tid = threadIdx.x;
    int w = tid >> 5;
    int lane = tid & 31;
    int g = lane >> 2;
    int tg = lane & 3;
    int row0 = bid * 128;
    float acc[8][4] = {};
    for (int k0 = 0; k0 < K; k0 += 32) {
        for (int l = tid; l < 1024; l += 256) {
            int r = l >> 3, c4 = l & 7;
            int nd = row0 + r;
            float4 v = make_float4(0.f, 0.f, 0.f, 0.f);
            if (nd < n) v = *reinterpret_cast<const float4*>(X + (size_t)nd * K + k0 + c4 * 4);
            *reinterpret_cast<float4*>(&Xs[r][c4 * 4]) = v;
        }
        for (int l = tid; l < 512; l += 256) {
            int kk = l >> 4, c4 = l & 15;
            *reinterpret_cast<float4*>(&Ws[kk][c4 * 4]) =
                *reinterpret_cast<const float4*>(W + (size_t)(k0 + kk) * 64 + c4 * 4);
        }
        __syncthreads();
#pragma unroll
        for (int kk = 0; kk < 32; kk += 8) {
            unsigned a0 = f2tf32(Xs[w * 16 + g][kk + tg]);
            unsigned a1 = f2tf32(Xs[w * 16 + g + 8][kk + tg]);
            unsigned a2 = f2tf32(Xs[w * 16 + g][kk + tg + 4]);
            unsigned a3 = f2tf32(Xs[w * 16 + g + 8][kk + tg + 4]);
#pragma unroll
            for (int ct = 0; ct < 8; ct++) {
                unsigned b0 = f2tf32(Ws[kk + tg][ct * 8 + g]);
                unsigned b1 = f2tf32(Ws[kk + tg + 4][ct * 8 + g]);
                mma_tf32(acc[ct][0], acc[ct][1], acc[ct][2], acc[ct][3],
                         a0, a1, a2, a3, b0, b1);
            }
        }
        __syncthreads();
    }
    int row_g = row0 + w * 16 + g;
    int row_g8 = row_g + 8;
    float ps_g = 0.f, pd_g = 0.f, ps_g8 = 0.f, pd_g8 = 0.f;
#pragma unroll
    for (int ct = 0; ct < 8; ct++) {
        int c0i = ct * 8 + 2 * tg;
        float s0 = att_s[c0i], s1 = att_s[c0i + 1];
        float d0 = att_d[c0i], d1 = att_d[c0i + 1];
        ps_g  += acc[ct][0] * s0 + acc[ct][1] * s1;
        pd_g  += acc[ct][0] * d0 + acc[ct][1] * d1;
        ps_g8 += acc[ct][2] * s0 + acc[ct][3] * s1;
        pd_g8 += acc[ct][2] * d0 + acc[ct][3] * d1;
    }
#pragma unroll
    for (int o = 1; o < 4; o <<= 1) {
        ps_g  += __shfl_xor_sync(FULLMASK, ps_g, o);
        pd_g  += __shfl_xor_sync(FULLMASK, pd_g, o);
        ps_g8 += __shfl_xor_sync(FULLMASK, ps_g8, o);
        pd_g8 += __shfl_xor_sync(FULLMASK, pd_g8, o);
    }
    if (row_g < n) {
#pragma unroll
        for (int ct = 0; ct < 8; ct++) {
            __half2 p = __floats2half2_rn(acc[ct][0], acc[ct][1]);
            *reinterpret_cast<__half2*>(C + (size_t)row_g * 64 + ct * 8 + 2 * tg) = p;
        }
        if (tg == 0) { as_[row_g] = ps_g; ad_[row_g] = pd_g; }
    }
    if (row_g8 < n) {
#pragma unroll
        for (int ct = 0; ct < 8; ct++) {
            __half2 p = __floats2half2_rn(acc[ct][2], acc[ct][3]);
            *reinterpret_cast<__half2*>(C + (size_t)row_g8 * 64 + ct * 8 + 2 * tg) = p;
        }
        if (tg == 0) { as_[row_g8] = ps_g8; ad_[row_g8] = pd_g8; }
    }
}

// ---------------- K1: zero both degree arrays --------------------------------
__global__ void zero2_kernel(int* __restrict__ d1, int* __restrict__ d2, int n) {
    int i = blockIdx.x * blockDim.x + threadIdx.x;
    if (i < n) { d1[i] = 0; d2[i] = 0; }
}

// ---------------- K2: gemm_score layer1  ||  hist1  ||  hist2 ----------------
__global__ void gemm1_hist_kernel(const float* __restrict__ X, const float* __restrict__ W,
        const float* __restrict__ att_s, const float* __restrict__ att_d,
        __half* __restrict__ C, float* __restrict__ as_, float* __restrict__ ad_, int n,
        int gemm_blocks,
        const int* __restrict__ dst1, int* __restrict__ deg1,
        const int* __restrict__ dst2, int* __restrict__ deg2, int ne, int hb) {
    int bid = blockIdx.x;
    if (bid < gemm_blocks) {
        gemm_score_body<FIN>(bid, X, W, att_s, att_d, C, as_, ad_, n);
        return;
    }
    bid -= gemm_blocks;
    const int* dstp; int* deg;
    if (bid < hb) { dstp = dst1; deg = deg1; }
    else          { bid -= hb; dstp = dst2; deg = deg2; }
    int base = (bid * blockDim.x + threadIdx.x) * 4;
    if (base + 3 < ne) {
        int4 d4 = *reinterpret_cast<const int4*>(dstp + base);
        atomicAdd(&deg[d4.x], 1);
        atomicAdd(&deg[d4.y], 1);
        atomicAdd(&deg[d4.z], 1);
        atomicAdd(&deg[d4.w], 1);
    } else {
        for (int i = base; i < ne; i++) atomicAdd(&deg[dstp[i]], 1);
    }
}

// ---------------- K3: per-chunk scan of both degree arrays -------------------
__global__ void scan_block2_kernel(const int* __restrict__ deg1, const int* __restrict__ deg2,
                                   int* __restrict__ rp1, int* __restrict__ rp2,
                                   int* __restrict__ bs1, int* __restrict__ bs2,
                                   int n, int sb) {
    __shared__ int tsum[256];
    int b = blockIdx.x;
    const int* deg; int* rowptr; int* bsum;
    if (b < sb) { deg = deg1; rowptr = rp1; bsum = bs1; }
    else        { b -= sb; deg = deg2; rowptr = rp2; bsum = bs2; }
    int t = threadIdx.x;
    int base = b * SCAN_CHUNK + t * 4;
    int v[4]; int s = 0;
#pragma unroll
    for (int j = 0; j < 4; j++) { v[j] = (base + j < n) ? deg[base + j] : 0; s += v[j]; }
    tsum[t] = s;
    __syncthreads();
    int acc = s;
    for (int off = 1; off < 256; off <<= 1) {
        int x = (t >= off) ? tsum[t - off] : 0;
        __syncthreads();
        tsum[t] += x;
        __syncthreads();
    }
    int excl = tsum[t] - acc;
    if (t == 255) bsum[b] = tsum[255];
    int run = excl;
#pragma unroll
    for (int j = 0; j < 4; j++) {
        if (base + j < n) rowptr[base + j] = run;
        run += v[j];
    }
}

// ---------------- K4: add chunk prefixes, init cur ---------------------------
__global__ void scan_add2_kernel(int* __restrict__ rp1, int* __restrict__ cur1,
                                 const int* __restrict__ bs1,
                                 int* __restrict__ rp2, int* __restrict__ cur2,
                                 const int* __restrict__ bs2,
                                 int n, int e, int node_blocks) {
    __shared__ int red[256];
    int b = blockIdx.x;
    int* rowptr; int* cur; const int* bsum;
    if (b < node_blocks) { rowptr = rp1; cur = cur1; bsum = bs1; }
    else                 { b -= node_blocks; rowptr = rp2; cur = cur2; bsum = bs2; }
    int t = threadIdx.x;
    int c = b >> 2;
    red[t] = (t < c) ? bsum[t] : 0;
    __syncthreads();
    for (int off = 128; off; off >>= 1) {
        if (t < off) red[t] += red[t + off];
        __syncthreads();
    }
    int prefix = red[0];
    int i = b * 256 + t;
    if (i < n) {
        int v = rowptr[i] + prefix;
        rowptr[i] = v;
        cur[i] = v;
    }
    if (b == 0 && t == 0) rowptr[n] = e;
}

// ---------------- K5: scatter layer 1 (int4, 4 edges/thread) -----------------
__global__ void scatter1_kernel(const int* __restrict__ src, const int* __restrict__ dst,
                                int* __restrict__ cur, int* __restrict__ csr, int ne) {
    int base = (blockIdx.x * blockDim.x + threadIdx.x) * 4;
    if (base + 3 < ne) {
        int4 s4 = *reinterpret_cast<const int4*>(src + base);
        int4 d4 = *reinterpret_cast<const int4*>(dst + base);
        int p;
        p = atomicAdd(&cur[d4.x], 1); csr[p] = s4.x;
        p = atomicAdd(&cur[d4.y], 1); csr[p] = s4.y;
        p = atomicAdd(&cur[d4.z], 1); csr[p] = s4.z;
        p = atomicAdd(&cur[d4.w], 1); csr[p] = s4.w;
    } else {
        for (int i = base; i < ne; i++) {
            int p = atomicAdd(&cur[dst[i]], 1);
            csr[p] = src[i];
        }
    }
}

// ---------- fused softmax + aggregation: HALF-WARP (16 lanes) per node -------
// lane owns 4 features (one uint2 = 2x half2 = 128B line per edge per group).
// flash-style online max (validated); all shfls use the half mask, width 16.
__device__ __forceinline__ void aggr_core16(const int* __restrict__ rowptr,
                                            const int* __restrict__ csr,
                                            const float* __restrict__ as_,
                                            const float* __restrict__ ad_,
                                            const uint2* __restrict__ h4v,
                                            int nd, int t, unsigned hmask,
                                            float& r0, float& r1, float& r2, float& r3) {
    int start = rowptr[nd];
    int end = rowptr[nd + 1];
    float adv = ad_[nd];
    float m = -CUDART_INF_F;
    float ssum = 0.f;
    float a0 = 0.f, a1 = 0.f, a2 = 0.f, a3 = 0.f;
    for (int base = start; base < end; base += 16) {
        int i = base + t;
        bool valid = (i < end);
        int s = valid ? csr[i] : 0;
        float e = -CUDART_INF_F;
        if (valid) {
            float v = as_[s] + adv;
            e = (v > 0.f) ? v : 0.2f * v;
        }
        float cm = e;
#pragma unroll
        for (int o = 8; o; o >>= 1) cm = fmaxf(cm, __shfl_xor_sync(hmask, cm, o, 16));
        float mnew = fmaxf(m, cm);
        float scale = __expf(m - mnew);
        ssum *= scale; a0 *= scale; a1 *= scale; a2 *= scale; a3 *= scale;
        float w = valid ? __expf(e - mnew) : 0.f;
        float ws = w;
#pragma unroll
        for (int o = 8; o; o >>= 1) ws += __shfl_xor_sync(hmask, ws, o, 16);
        ssum += ws;
        m = mnew;
        int cnt = min(16, end - base);
        for (int j = 0; j < cnt; j += 8) {      // invalid lanes carry w=0, s=0
            float wv[8]; uint2 hr[8];
#pragma unroll
            for (int k = 0; k < 8; k++) {
                int sj = __shfl_sync(hmask, s, j + k, 16);
                wv[k] = __shfl_sync(hmask, w, j + k, 16);
                hr[k] = h4v[(size_t)sj * 16 + t];
            }
#pragma unroll
            for (int k = 0; k < 8; k++) {
                float2 lo = __half22float2(*reinterpret_cast<__half2*>(&hr[k].x));
                float2 hi = __half22float2(*reinterpret_cast<__half2*>(&hr[k].y));
                a0 += wv[k] * lo.x; a1 += wv[k] * lo.y;
                a2 += wv[k] * hi.x; a3 += wv[k] * hi.y;
            }
        }
    }
    float inv = 1.f / (ssum + 1e-16f);
    r0 = a0 * inv; r1 = a1 * inv; r2 = a2 * inv; r3 = a3 * inv;
}

// ---------------- K6: aggr layer1 (+bias+relu)  ||  scatter layer2 -----------
// first agg_blocks: 8 warps x 2 nodes per block (16 nodes/block).
__global__ void aggr_scatter_kernel(const int* __restrict__ rowptr, const int* __restrict__ csr,
        const float* __restrict__ as_, const float* __restrict__ ad_,
        const uint2* __restrict__ h4v, const float* __restrict__ bias,
        float* __restrict__ aggout, int n, int agg_blocks,
        const int* __restrict__ src2, const int* __restrict__ dst2,
        int* __restrict__ cur2, int* __restrict__ csr2, int ne) {
    int b = blockIdx.x;
    if (b >= agg_blocks) {                 // scatter for layer 2
        b -= agg_blocks;
        int i = b * blockDim.x + threadIdx.x;
        if (i < ne) {
            int d = dst2[i];
            int p = atomicAdd(&cur2[d], 1);
            csr2[p] = src2[i];
        }
        return;
    }
    int tid = threadIdx.x;
    int lane = tid & 31;
    int half = lane >> 4;
    int t = lane & 15;
    unsigned hmask = 0xFFFFu << (half * 16);
    int nd = (b * 8 + (tid >> 5)) * 2 + half;
    if (nd >= n) return;
    float r0, r1, r2, r3;
    aggr_core16(rowptr, csr, as_, ad_, h4v, nd, t, hmask, r0, r1, r2, r3);
    float4 bq = *reinterpret_cast<const float4*>(bias + t * 4);
    r0 = fmaxf(r0 + bq.x, 0.f);
    r1 = fmaxf(r1 + bq.y, 0.f);
    r2 = fmaxf(r2 + bq.z, 0.f);
    r3 = fmaxf(r3 + bq.w, 0.f);
    *reinterpret_cast<float4*>(aggout + (size_t)nd * 64 + t * 4) = make_float4(r0, r1, r2, r3);
}

// ---------------- K7: gemm_score layer2 --------------------------------------
__global__ void gemm2_kernel(const float* __restrict__ X, const float* __restrict__ W,
        const float* __restrict__ att_s, const float* __restrict__ att_d,
        __half* __restrict__ C, float* __restrict__ as_, float* __restrict__ ad_, int n) {
    gemm_score_body<HID>(blockIdx.x, X, W, att_s, att_d, C, as_, ad_, n);
}

// ---------------- K8: aggr layer2 + bias + linear + log_softmax --------------
// half-warp per node; lane t owns output cols 2t, 2t+1.
__global__ void aggr_final_kernel(const int* __restrict__ rowptr, const int* __restrict__ csr,
        const float* __restrict__ as_, const float* __restrict__ ad_,
        const uint2* __restrict__ h4v, const float* __restrict__ bias,
        const float* __restrict__ Wlin, const float* __restrict__ blin,
        float* __restrict__ out, int n) {
    __shared__ float Ws[64 * 32];
    for (int i = threadIdx.x; i < 64 * 32; i += blockDim.x) Ws[i] = Wlin[i];
    __syncthreads();
    int tid = threadIdx.x;
    int lane = tid & 31;
    int half = lane >> 4;
    int t = lane & 15;
    unsigned hmask = 0xFFFFu << (half * 16);
    int nd = (blockIdx.x * 8 + (tid >> 5)) * 2 + half;
    if (nd >= n) return;
    float r0, r1, r2, r3;
    aggr_core16(rowptr, csr, as_, ad_, h4v, nd, t, hmask, r0, r1, r2, r3);
    float4 bq = *reinterpret_cast<const float4*>(bias + t * 4);
    r0 += bq.x; r1 += bq.y; r2 += bq.z; r3 += bq.w;
    // y[c] = blin[c] + sum_k row[k]*Wlin[k][c]; row[4j+q] lives on lane j (q=0..3)
    float y0 = blin[2 * t], y1 = blin[2 * t + 1];
#pragma unroll
    for (int j = 0; j < 16; j++) {
        float q0 = __shfl_sync(hmask, r0, j, 16);
        float q1 = __shfl_sync(hmask, r1, j, 16);
        float q2 = __shfl_sync(hmask, r2, j, 16);
        float q3 = __shfl_sync(hmask, r3, j, 16);
        const float* w0 = &Ws[(4 * j) * 32 + 2 * t];
        y0 += q0 * w0[0]   + q1 * w0[32]   + q2 * w0[64]   + q3 * w0[96];
        y1 += q0 * w0[1]   + q1 * w0[33]   + q2 * w0[65]   + q3 * w0[97];
    }
    float m = fmaxf(y0, y1);
#pragma unroll
    for (int o = 8; o; o >>= 1) m = fmaxf(m, __shfl_xor_sync(hmask, m, o, 16));
    float ss = __expf(y0 - m) + __expf(y1 - m);
#pragma unroll
    for (int o = 8; o; o >>= 1) ss += __shfl_xor_sync(hmask, ss, o, 16);
    float ls = __logf(ss);
    out[(size_t)nd * 32 + 2 * t]     = y0 - m - ls;
    out[(size_t)nd * 32 + 2 * t + 1] = y1 - m - ls;
}

// ---------------- launch ------------------------------------------------------
extern "C" void kernel_launch(void* const* d_in, const int* in_sizes, int n_in,
                              void* d_out, int out_size) {
    const float* x        = (const float*)d_in[0];
    const int*   ei1      = (const int*)d_in[1];
    const int*   ei2      = (const int*)d_in[2];
    const float* W1       = (const float*)d_in[3];
    const float* att_src1 = (const float*)d_in[4];
    const float* att_dst1 = (const float*)d_in[5];
    const float* b1       = (const float*)d_in[6];
    const float* W2       = (const float*)d_in[7];
    const float* att_src2 = (const float*)d_in[8];
    const float* att_dst2 = (const float*)d_in[9];
    const float* b2       = (const float*)d_in[10];
    const float* Wlin     = (const float*)d_in[11];
    const float* blin     = (const float*)d_in[12];
    float* out = (float*)d_out;

    const int n = in_sizes[0] / FIN;       // 100000
    const int e = in_sizes[1] / 2;         // 1600000

    __half* h;
    float *agg, *as_, *ad_;
    int *deg1, *rp1, *cur1, *csr1, *bs1;
    int *deg2, *rp2, *cur2, *csr2, *bs2;
    cudaGetSymbolAddress((void**)&h,    g_h);
    cudaGetSymbolAddress((void**)&agg,  g_agg);
    cudaGetSymbolAddress((void**)&as_,  g_as);
    cudaGetSymbolAddress((void**)&ad_,  g_ad);
    cudaGetSymbolAddress((void**)&deg1, g_deg1);
    cudaGetSymbolAddress((void**)&rp1,  g_rp1);
    cudaGetSymbolAddress((void**)&cur1, g_cur1);
    cudaGetSymbolAddress((void**)&csr1, g_csr1);
    cudaGetSymbolAddress((void**)&bs1,  g_bsum1);
    cudaGetSymbolAddress((void**)&deg2, g_deg2);
    cudaGetSymbolAddress((void**)&rp2,  g_rp2);
    cudaGetSymbolAddress((void**)&cur2, g_cur2);
    cudaGetSymbolAddress((void**)&csr2, g_csr2);
    cudaGetSymbolAddress((void**)&bs2,  g_bsum2);
    const uint2* h4v = (const uint2*)h;

    const int TB = 256;
    int gemm_blocks = (n + 127) / 128;                   // 782
    int node_blocks = (n + TB - 1) / TB;                 // 391
    int agg_blocks  = (n + 15) / 16;                     // 6250 (16 nodes/block)
    int eb          = (e + TB - 1) / TB;                 // 6250
    int hb          = (e + 4 * TB - 1) / (4 * TB);       // 1563
    int sb          = (n + SCAN_CHUNK - 1) / SCAN_CHUNK; // 98

    // K1: zero degree arrays
    zero2_kernel<<<node_blocks, TB>>>(deg1, deg2, n);
    // K2: gemm1+score1 || hist1 || hist2
    gemm1_hist_kernel<<<gemm_blocks + 2 * hb, TB>>>(
        x, W1, att_src1, att_dst1, h, as_, ad_, n, gemm_blocks,
        ei1 + e, deg1, ei2 + e, deg2, e, hb);
    // K3/K4: rowptr scans (both layers)
    scan_block2_kernel<<<2 * sb, TB>>>(deg1, deg2, rp1, rp2, bs1, bs2, n, sb);
    scan_add2_kernel<<<2 * node_blocks, TB>>>(rp1, cur1, bs1, rp2, cur2, bs2, n, e, node_blocks);
    // K5: scatter layer 1 (int4)
    scatter1_kernel<<<hb, TB>>>(ei1, ei1 + e, cur1, csr1, e);
    // K6: aggr layer1 (+bias+relu)  ||  scatter layer 2
    aggr_scatter_kernel<<<agg_blocks + eb, TB>>>(
        rp1, csr1, as_, ad_, h4v, b1, agg, n, agg_blocks,
        ei2, ei2 + e, cur2, csr2, e);
    // K7: gemm2+score2
    gemm2_kernel<<<gemm_blocks, TB>>>(agg, W2, att_src2, att_dst2, h, as_, ad_, n);
    // K8: aggr layer2 + linear + log_softmax
    aggr_final_kernel<<<agg_blocks, TB>>>(
        rp2, csr2, as_, ad_, h4v, b2, Wlin, blin, out, n);
}

// round 14
// speedup vs baseline: 1.3952x; 1.0658x over previous
#include <cuda_runtime.h>
#include <cuda_bf16.h>
#include <cuda_fp16.h>
#include <math_constants.h>

#define FIN 128
#define HID 64
#define NNODES 100000
#define NEDGES 1600000
#define SCAN_CHUNK 1024
#define FULLMASK 0xFFFFFFFFu

// ---------------- scratch (static device globals; no allocation) -------------
__device__ __align__(256) __half g_h[NNODES * HID];   // fp16 gather source
__device__ __align__(256) float g_agg[NNODES * HID];
__device__ __align__(256) float g_as[NNODES];
__device__ __align__(256) float g_ad[NNODES];
__device__ __align__(256) int g_deg1[NNODES],        g_deg2[NNODES];
__device__ __align__(256) int g_rp1[NNODES + 1],     g_rp2[NNODES + 1];
__device__ __align__(256) int g_cur1[NNODES],        g_cur2[NNODES];
__device__ __align__(256) int g_csr1[NEDGES],        g_csr2[NEDGES];
__device__ __align__(256) int g_bsum1[256],          g_bsum2[256];

// ---------------- tf32 helpers ------------------------------------------------
__device__ __forceinline__ unsigned f2tf32(float f) {
    unsigned u;
    asm("cvt.rna.tf32.f32 %0, %1;" : "=r"(u) : "f"(f));
    return u;
}
__device__ __forceinline__ void mma_tf32(float& c0, float& c1, float& c2, float& c3,
                                         unsigned a0, unsigned a1, unsigned a2, unsigned a3,
                                         unsigned b0, unsigned b1) {
    asm volatile(
        "mma.sync.aligned.m16n8k8.row.col.f32.tf32.tf32.f32 "
        "{%0,%1,%2,%3}, {%4,%5,%6,%7}, {%8,%9}, {%0,%1,%2,%3};"
        : "+f"(c0), "+f"(c1), "+f"(c2), "+f"(c3)
        : "r"(a0), "r"(a1), "r"(a2), "r"(a3), "r"(b0), "r"(b1));
}

// ---------------- GEMM (tf32 MMA) + fused attention scores --------------------
template <int K>
__device__ __forceinline__ void gemm_score_body(int bid,
        const float* __restrict__ X, const float* __restrict__ W,
        const float* __restrict__ att_s, const float* __restrict__ att_d,
        __half* __restrict__ C, float* __restrict__ as_, float* __restrict__ ad_,
        int n) {
    __shared__ float Xs[128][36];
    __shared__ float Ws[32][72];
    int tid = threadIdx.x;
    int w = tid >> 5;
    int lane = tid & 31;
    int g = lane >> 2;
    int tg = lane & 3;
    int row0 = bid * 128;
    float acc[8][4] = {};
    for (int k0 = 0; k0 < K; k0 += 32) {
        for (int l = tid; l < 1024; l += 256) {
            int r = l >> 3, c4 = l & 7;
            int nd = row0 + r;
            float4 v = make_float4(0.f, 0.f, 0.f, 0.f);
            if (nd < n) v = *reinterpret_cast<const float4*>(X + (size_t)nd * K + k0 + c4 * 4);
            *reinterpret_cast<float4*>(&Xs[r][c4 * 4]) = v;
        }
        for (int l = tid; l < 512; l += 256) {
            int kk = l >> 4, c4 = l & 15;
            *reinterpret_cast<float4*>(&Ws[kk][c4 * 4]) =
                *reinterpret_cast<const float4*>(W + (size_t)(k0 + kk) * 64 + c4 * 4);
        }
        __syncthreads();
#pragma unroll
        for (int kk = 0; kk < 32; kk += 8) {
            unsigned a0 = f2tf32(Xs[w * 16 + g][kk + tg]);
            unsigned a1 = f2tf32(Xs[w * 16 + g + 8][kk + tg]);
            unsigned a2 = f2tf32(Xs[w * 16 + g][kk + tg + 4]);
            unsigned a3 = f2tf32(Xs[w * 16 + g + 8][kk + tg + 4]);
#pragma unroll
            for (int ct = 0; ct < 8; ct++) {
                unsigned b0 = f2tf32(Ws[kk + tg][ct * 8 + g]);
                unsigned b1 = f2tf32(Ws[kk + tg + 4][ct * 8 + g]);
                mma_tf32(acc[ct][0], acc[ct][1], acc[ct][2], acc[ct][3],
                         a0, a1, a2, a3, b0, b1);
            }
        }
        __syncthreads();
    }
    int row_g = row0 + w * 16 + g;
    int row_g8 = row_g + 8;
    float ps_g = 0.f, pd_g = 0.f, ps_g8 = 0.f, pd_g8 = 0.f;
#pragma unroll
    for (int ct = 0; ct < 8; ct++) {
        int c0i = ct * 8 + 2 * tg;
        float s0 = att_s[c0i], s1 = att_s[c0i + 1];
        float d0 = att_d[c0i], d1 = att_d[c0i + 1];
        ps_g  += acc[ct][0] * s0 + acc[ct][1] * s1;
        pd_g  += acc[ct][0] * d0 + acc[ct][1] * d1;
        ps_g8 += acc[ct][2] * s0 + acc[ct][3] * s1;
        pd_g8 += acc[ct][2] * d0 + acc[ct][3] * d1;
    }
#pragma unroll
    for (int o = 1; o < 4; o <<= 1) {
        ps_g  += __shfl_xor_sync(FULLMASK, ps_g, o);
        pd_g  += __shfl_xor_sync(FULLMASK, pd_g, o);
        ps_g8 += __shfl_xor_sync(FULLMASK, ps_g8, o);
        pd_g8 += __shfl_xor_sync(FULLMASK, pd_g8, o);
    }
    if (row_g < n) {
#pragma unroll
        for (int ct = 0; ct < 8; ct++) {
            __half2 p = __floats2half2_rn(acc[ct][0], acc[ct][1]);
            *reinterpret_cast<__half2*>(C + (size_t)row_g * 64 + ct * 8 + 2 * tg) = p;
        }
        if (tg == 0) { as_[row_g] = ps_g; ad_[row_g] = pd_g; }
    }
    if (row_g8 < n) {
#pragma unroll
        for (int ct = 0; ct < 8; ct++) {
            __half2 p = __floats2half2_rn(acc[ct][2], acc[ct][3]);
            *reinterpret_cast<__half2*>(C + (size_t)row_g8 * 64 + ct * 8 + 2 * tg) = p;
        }
        if (tg == 0) { as_[row_g8] = ps_g8; ad_[row_g8] = pd_g8; }
    }
}

// ---------------- K1: zero both degree arrays --------------------------------
__global__ void zero2_kernel(int* __restrict__ d1, int* __restrict__ d2, int n) {
    int i = blockIdx.x * blockDim.x + threadIdx.x;
    if (i < n) { d1[i] = 0; d2[i] = 0; }
}

// ---------------- K2: gemm_score layer1  ||  hist1  ||  hist2 ----------------
__global__ void gemm1_hist_kernel(const float* __restrict__ X, const float* __restrict__ W,
        const float* __restrict__ att_s, const float* __restrict__ att_d,
        __half* __restrict__ C, float* __restrict__ as_, float* __restrict__ ad_, int n,
        int gemm_blocks,
        const int* __restrict__ dst1, int* __restrict__ deg1,
        const int* __restrict__ dst2, int* __restrict__ deg2, int ne, int hb) {
    int bid = blockIdx.x;
    if (bid < gemm_blocks) {
        gemm_score_body<FIN>(bid, X, W, att_s, att_d, C, as_, ad_, n);
        return;
    }
    bid -= gemm_blocks;
    const int* dstp; int* deg;
    if (bid < hb) { dstp = dst1; deg = deg1; }
    else          { bid -= hb; dstp = dst2; deg = deg2; }
    int base = (bid * blockDim.x + threadIdx.x) * 4;
    if (base + 3 < ne) {
        int4 d4 = *reinterpret_cast<const int4*>(dstp + base);
        atomicAdd(&deg[d4.x], 1);
        atomicAdd(&deg[d4.y], 1);
        atomicAdd(&deg[d4.z], 1);
        atomicAdd(&deg[d4.w], 1);
    } else {
        for (int i = base; i < ne; i++) atomicAdd(&deg[dstp[i]], 1);
    }
}

// ---------------- K3: per-chunk scan of both degree arrays -------------------
__global__ void scan_block2_kernel(const int* __restrict__ deg1, const int* __restrict__ deg2,
                                   int* __restrict__ rp1, int* __restrict__ rp2,
                                   int* __restrict__ bs1, int* __restrict__ bs2,
                                   int n, int sb) {
    __shared__ int tsum[256];
    int b = blockIdx.x;
    const int* deg; int* rowptr; int* bsum;
    if (b < sb) { deg = deg1; rowptr = rp1; bsum = bs1; }
    else        { b -= sb; deg = deg2; rowptr = rp2; bsum = bs2; }
    int t = threadIdx.x;
    int base = b * SCAN_CHUNK + t * 4;
    int v[4]; int s = 0;
#pragma unroll
    for (int j = 0; j < 4; j++) { v[j] = (base + j < n) ? deg[base + j] : 0; s += v[j]; }
    tsum[t] = s;
    __syncthreads();
    int acc = s;
    for (int off = 1; off < 256; off <<= 1) {
        int x = (t >= off) ? tsum[t - off] : 0;
        __syncthreads();
        tsum[t] += x;
        __syncthreads();
    }
    int excl = tsum[t] - acc;
    if (t == 255) bsum[b] = tsum[255];
    int run = excl;
#pragma unroll
    for (int j = 0; j < 4; j++) {
        if (base + j < n) rowptr[base + j] = run;
        run += v[j];
    }
}

// ---------------- K4: add chunk prefixes, init cur ---------------------------
__global__ void scan_add2_kernel(int* __restrict__ rp1, int* __restrict__ cur1,
                                 const int* __restrict__ bs1,
                                 int* __restrict__ rp2, int* __restrict__ cur2,
                                 const int* __restrict__ bs2,
                                 int n, int e, int node_blocks) {
    __shared__ int red[256];
    int b = blockIdx.x;
    int* rowptr; int* cur; const int* bsum;
    if (b < node_blocks) { rowptr = rp1; cur = cur1; bsum = bs1; }
    else                 { b -= node_blocks; rowptr = rp2; cur = cur2; bsum = bs2; }
    int t = threadIdx.x;
    int c = b >> 2;
    red[t] = (t < c) ? bsum[t] : 0;
    __syncthreads();
    for (int off = 128; off; off >>= 1) {
        if (t < off) red[t] += red[t + off];
        __syncthreads();
    }
    int prefix = red[0];
    int i = b * 256 + t;
    if (i < n) {
        int v = rowptr[i] + prefix;
        rowptr[i] = v;
        cur[i] = v;
    }
    if (b == 0 && t == 0) rowptr[n] = e;
}

// ---------------- K5: scatter layer 1 (int4, 4 edges/thread) -----------------
__global__ void scatter1_kernel(const int* __restrict__ src, const int* __restrict__ dst,
                                int* __restrict__ cur, int* __restrict__ csr, int ne) {
    int base = (blockIdx.x * blockDim.x + threadIdx.x) * 4;
    if (base + 3 < ne) {
        int4 s4 = *reinterpret_cast<const int4*>(src + base);
        int4 d4 = *reinterpret_cast<const int4*>(dst + base);
        int p;
        p = atomicAdd(&cur[d4.x], 1); csr[p] = s4.x;
        p = atomicAdd(&cur[d4.y], 1); csr[p] = s4.y;
        p = atomicAdd(&cur[d4.z], 1); csr[p] = s4.z;
        p = atomicAdd(&cur[d4.w], 1); csr[p] = s4.w;
    } else {
        for (int i = base; i < ne; i++) {
            int p = atomicAdd(&cur[dst[i]], 1);
            csr[p] = src[i];
        }
    }
}

// ---------- fused softmax + aggregation: QUARTER-WARP (8 lanes) per node -----
// lane owns 8 features (one uint4 = 4x half2 = 128B line per edge per group).
// flash-style online max (validated); all shfls use the group mask, width 8.
__device__ __forceinline__ void aggr_core8(const int* __restrict__ rowptr,
                                           const int* __restrict__ csr,
                                           const float* __restrict__ as_,
                                           const float* __restrict__ ad_,
                                           const uint4* __restrict__ h8v,
                                           int nd, int t, unsigned qmask,
                                           float* r) {
    int start = rowptr[nd];
    int end = rowptr[nd + 1];
    float adv = ad_[nd];
    float m = -CUDART_INF_F;
    float ssum = 0.f;
    float a[8] = {};
    for (int base = start; base < end; base += 8) {
        int i = base + t;
        bool valid = (i < end);
        int s = valid ? csr[i] : 0;
        float e = -CUDART_INF_F;
        if (valid) {
            float v = as_[s] + adv;
            e = (v > 0.f) ? v : 0.2f * v;
        }
        float cm = e;
#pragma unroll
        for (int o = 4; o; o >>= 1) cm = fmaxf(cm, __shfl_xor_sync(qmask, cm, o, 8));
        float mnew = fmaxf(m, cm);
        float scale = __expf(m - mnew);
        ssum *= scale;
#pragma unroll
        for (int k = 0; k < 8; k++) a[k] *= scale;
        float w = valid ? __expf(e - mnew) : 0.f;
        float ws = w;
#pragma unroll
        for (int o = 4; o; o >>= 1) ws += __shfl_xor_sync(qmask, ws, o, 8);
        ssum += ws;
        m = mnew;
        // gather batch: all 8 edges of this chunk (invalid lanes: w=0, s=0)
        float wv[8]; uint4 hr[8];
#pragma unroll
        for (int k = 0; k < 8; k++) {
            int sj = __shfl_sync(qmask, s, k, 8);
            wv[k] = __shfl_sync(qmask, w, k, 8);
            hr[k] = h8v[(size_t)sj * 8 + t];
        }
#pragma unroll
        for (int k = 0; k < 8; k++) {
            float2 f0 = __half22float2(*reinterpret_cast<__half2*>(&hr[k].x));
            float2 f1 = __half22float2(*reinterpret_cast<__half2*>(&hr[k].y));
            float2 f2 = __half22float2(*reinterpret_cast<__half2*>(&hr[k].z));
            float2 f3 = __half22float2(*reinterpret_cast<__half2*>(&hr[k].w));
            a[0] += wv[k] * f0.x; a[1] += wv[k] * f0.y;
            a[2] += wv[k] * f1.x; a[3] += wv[k] * f1.y;
            a[4] += wv[k] * f2.x; a[5] += wv[k] * f2.y;
            a[6] += wv[k] * f3.x; a[7] += wv[k] * f3.y;
        }
    }
    float inv = 1.f / (ssum + 1e-16f);
#pragma unroll
    for (int k = 0; k < 8; k++) r[k] = a[k] * inv;
}

// ---------------- K6: aggr layer1 (+bias+relu)  ||  scatter layer2 -----------
// first agg_blocks: 8 warps x 4 nodes per block (32 nodes/block).
__global__ void aggr_scatter_kernel(const int* __restrict__ rowptr, const int* __restrict__ csr,
        const float* __restrict__ as_, const float* __restrict__ ad_,
        const uint4* __restrict__ h8v, const float* __restrict__ bias,
        float* __restrict__ aggout, int n, int agg_blocks,
        const int* __restrict__ src2, const int* __restrict__ dst2,
        int* __restrict__ cur2, int* __restrict__ csr2, int ne) {
    int b = blockIdx.x;
    if (b >= agg_blocks) {                 // scatter for layer 2
        b -= agg_blocks;
        int i = b * blockDim.x + threadIdx.x;
        if (i < ne) {
            int d = dst2[i];
            int p = atomicAdd(&cur2[d], 1);
            csr2[p] = src2[i];
        }
        return;
    }
    int tid = threadIdx.x;
    int lane = tid & 31;
    int q = lane >> 3;
    int t = lane & 7;
    unsigned qmask = 0xFFu << (q * 8);
    int nd = (b * 8 + (tid >> 5)) * 4 + q;
    if (nd >= n) return;
    float r[8];
    aggr_core8(rowptr, csr, as_, ad_, h8v, nd, t, qmask, r);
    float4 b0 = *reinterpret_cast<const float4*>(bias + t * 8);
    float4 b1 = *reinterpret_cast<const float4*>(bias + t * 8 + 4);
    float4 o0 = make_float4(fmaxf(r[0] + b0.x, 0.f), fmaxf(r[1] + b0.y, 0.f),
                            fmaxf(r[2] + b0.z, 0.f), fmaxf(r[3] + b0.w, 0.f));
    float4 o1 = make_float4(fmaxf(r[4] + b1.x, 0.f), fmaxf(r[5] + b1.y, 0.f),
                            fmaxf(r[6] + b1.z, 0.f), fmaxf(r[7] + b1.w, 0.f));
    *reinterpret_cast<float4*>(aggout + (size_t)nd * 64 + t * 8)     = o0;
    *reinterpret_cast<float4*>(aggout + (size_t)nd * 64 + t * 8 + 4) = o1;
}

// ---------------- K7: gemm_score layer2 --------------------------------------
__global__ void gemm2_kernel(const float* __restrict__ X, const float* __restrict__ W,
        const float* __restrict__ att_s, const float* __restrict__ att_d,
        __half* __restrict__ C, float* __restrict__ as_, float* __restrict__ ad_, int n) {
    gemm_score_body<HID>(blockIdx.x, X, W, att_s, att_d, C, as_, ad_, n);
}

// ---------------- K8: aggr layer2 + bias + linear + log_softmax --------------
// quarter-warp per node; lane t owns output cols 4t..4t+3.
__global__ void aggr_final_kernel(const int* __restrict__ rowptr, const int* __restrict__ csr,
        const float* __restrict__ as_, const float* __restrict__ ad_,
        const uint4* __restrict__ h8v, const float* __restrict__ bias,
        const float* __restrict__ Wlin, const float* __restrict__ blin,
        float* __restrict__ out, int n) {
    __shared__ float Ws[64 * 32];
    for (int i = threadIdx.x; i < 64 * 32; i += blockDim.x) Ws[i] = Wlin[i];
    __syncthreads();
    int tid = threadIdx.x;
    int lane = tid & 31;
    int q = lane >> 3;
    int t = lane & 7;
    unsigned qmask = 0xFFu << (q * 8);
    int nd = (blockIdx.x * 8 + (tid >> 5)) * 4 + q;
    if (nd >= n) return;
    float r[8];
    aggr_core8(rowptr, csr, as_, ad_, h8v, nd, t, qmask, r);
    float4 bq0 = *reinterpret_cast<const float4*>(bias + t * 8);
    float4 bq1 = *reinterpret_cast<const float4*>(bias + t * 8 + 4);
    r[0] += bq0.x; r[1] += bq0.y; r[2] += bq0.z; r[3] += bq0.w;
    r[4] += bq1.x; r[5] += bq1.y; r[6] += bq1.z; r[7] += bq1.w;
    // y[c] = blin[c] + sum_k row[k]*Wlin[k][c]; row[8j+q] lives on lane j (q=0..7)
    float4 y = *reinterpret_cast<const float4*>(blin + 4 * t);
#pragma unroll
    for (int j = 0; j < 8; j++) {
#pragma unroll
        for (int kq = 0; kq < 8; kq++) {
            float rv = __shfl_sync(qmask, r[kq], j, 8);
            const float* wr = &Ws[(8 * j + kq) * 32 + 4 * t];
            y.x += rv * wr[0];
            y.y += rv * wr[1];
            y.z += rv * wr[2];
            y.w += rv * wr[3];
        }
    }
    float m = fmaxf(fmaxf(y.x, y.y), fmaxf(y.z, y.w));
#pragma unroll
    for (int o = 4; o; o >>= 1) m = fmaxf(m, __shfl_xor_sync(qmask, m, o, 8));
    float ss = __expf(y.x - m) + __expf(y.y - m) + __expf(y.z - m) + __expf(y.w - m);
#pragma unroll
    for (int o = 4; o; o >>= 1) ss += __shfl_xor_sync(qmask, ss, o, 8);
    float ls = m + __logf(ss);
    float4 ov = make_float4(y.x - ls, y.y - ls, y.z - ls, y.w - ls);
    *reinterpret_cast<float4*>(out + (size_t)nd * 32 + 4 * t) = ov;
}

// ---------------- launch ------------------------------------------------------
extern "C" void kernel_launch(void* const* d_in, const int* in_sizes, int n_in,
                              void* d_out, int out_size) {
    const float* x        = (const float*)d_in[0];
    const int*   ei1      = (const int*)d_in[1];
    const int*   ei2      = (const int*)d_in[2];
    const float* W1       = (const float*)d_in[3];
    const float* att_src1 = (const float*)d_in[4];
    const float* att_dst1 = (const float*)d_in[5];
    const float* b1       = (const float*)d_in[6];
    const float* W2       = (const float*)d_in[7];
    const float* att_src2 = (const float*)d_in[8];
    const float* att_dst2 = (const float*)d_in[9];
    const float* b2       = (const float*)d_in[10];
    const float* Wlin     = (const float*)d_in[11];
    const float* blin     = (const float*)d_in[12];
    float* out = (float*)d_out;

    const int n = in_sizes[0] / FIN;       // 100000
    const int e = in_sizes[1] / 2;         // 1600000

    __half* h;
    float *agg, *as_, *ad_;
    int *deg1, *rp1, *cur1, *csr1, *bs1;
    int *deg2, *rp2, *cur2, *csr2, *bs2;
    cudaGetSymbolAddress((void**)&h,    g_h);
    cudaGetSymbolAddress((void**)&agg,  g_agg);
    cudaGetSymbolAddress((void**)&as_,  g_as);
    cudaGetSymbolAddress((void**)&ad_,  g_ad);
    cudaGetSymbolAddress((void**)&deg1, g_deg1);
    cudaGetSymbolAddress((void**)&rp1,  g_rp1);
    cudaGetSymbolAddress((void**)&cur1, g_cur1);
    cudaGetSymbolAddress((void**)&csr1, g_csr1);
    cudaGetSymbolAddress((void**)&bs1,  g_bsum1);
    cudaGetSymbolAddress((void**)&deg2, g_deg2);
    cudaGetSymbolAddress((void**)&rp2,  g_rp2);
    cudaGetSymbolAddress((void**)&cur2, g_cur2);
    cudaGetSymbolAddress((void**)&csr2, g_csr2);
    cudaGetSymbolAddress((void**)&bs2,  g_bsum2);
    const uint4* h8v = (const uint4*)h;

    const int TB = 256;
    int gemm_blocks = (n + 127) / 128;                   // 782
    int node_blocks = (n + TB - 1) / TB;                 // 391
    int agg_blocks  = (n + 31) / 32;                     // 3125 (32 nodes/block)
    int eb          = (e + TB - 1) / TB;                 // 6250
    int hb          = (e + 4 * TB - 1) / (4 * TB);       // 1563
    int sb          = (n + SCAN_CHUNK - 1) / SCAN_CHUNK; // 98

    // K1: zero degree arrays
    zero2_kernel<<<node_blocks, TB>>>(deg1, deg2, n);
    // K2: gemm1+score1 || hist1 || hist2
    gemm1_hist_kernel<<<gemm_blocks + 2 * hb, TB>>>(
        x, W1, att_src1, att_dst1, h, as_, ad_, n, gemm_blocks,
        ei1 + e, deg1, ei2 + e, deg2, e, hb);
    // K3/K4: rowptr scans (both layers)
    scan_block2_kernel<<<2 * sb, TB>>>(deg1, deg2, rp1, rp2, bs1, bs2, n, sb);
    scan_add2_kernel<<<2 * node_blocks, TB>>>(rp1, cur1, bs1, rp2, cur2, bs2, n, e, node_blocks);
    // K5: scatter layer 1 (int4)
    scatter1_kernel<<<hb, TB>>>(ei1, ei1 + e, cur1, csr1, e);
    // K6: aggr layer1 (+bias+relu)  ||  scatter layer 2
    aggr_scatter_kernel<<<agg_blocks + eb, TB>>>(
        rp1, csr1, as_, ad_, h8v, b1, agg, n, agg_blocks,
        ei2, ei2 + e, cur2, csr2, e);
    // K7: gemm2+score2
    gemm2_kernel<<<gemm_blocks, TB>>>(agg, W2, att_src2, att_dst2, h, as_, ad_, n);
    // K8: aggr layer2 + linear + log_softmax
    aggr_final_kernel<<<agg_blocks, TB>>>(
        rp2, csr2, as_, ad_, h8v, b2, Wlin, blin, out, n);
}